// round 6
// baseline (speedup 1.0000x reference)
#include <cuda_runtime.h>

// Zero-insertion unpool (stride-2 "bed of nails"), NHWC, C=64.
// out[b, 2h, 2w, c] = x[b, h, w, c]; everything else 0.
//
// x:   (32, 112, 112, 64) f32
// out: (32, 224, 224, 64) f32
//
// Input-centric streaming kernel: each thread loads one input float4 and
// issues 4 independent float4 stores (data + 3 zero blocks covering the
// 2x2 output footprint of that input pixel's channel slice).
//
//   out row 2*ih : [pixel 2*iw -> data][pixel 2*iw+1 -> zero]
//   out row 2*ih+1: [zero][zero]
//
// All four store offsets are compile-time immediates from one base, every
// load lane is active, and each warp's stores are 256B-contiguous per
// half-warp at each offset (fully coalesced 128B sectors).

static constexpr int H_IN   = 112;
static constexpr int W_IN   = 112;
static constexpr int H_OUT  = 224;
static constexpr int C4     = 16;              // float4 per pixel (C=64)
static constexpr int IROW4  = W_IN * C4;       // float4 per input row = 1792
static constexpr int OROW4  = H_OUT * C4 * 2 / 2; // = 224*16 = 3584 float4 per output row
static constexpr int TPB    = 256;

__global__ __launch_bounds__(TPB)
void unpool_kernel(const float4* __restrict__ x, float4* __restrict__ out) {
    const int r4 = blockIdx.x * TPB + threadIdx.x;  // 0 .. IROW4-1 (float4 within input row)
    const int ih = blockIdx.y;                      // 0 .. 111
    const int b  = blockIdx.z;                      // 0 .. 31

    const int iw = r4 >> 4;       // input pixel in row
    const int cv = r4 & 15;       // float4 within 64-ch pixel

    // Dense, fully-coalesced streaming load (no reuse -> evict-first).
    const float4 v = __ldcs(&x[(b * H_IN + ih) * IROW4 + r4]);
    const float4 z = make_float4(0.f, 0.f, 0.f, 0.f);

    // Output base: row 2*ih, pixel 2*iw, channel-vec cv.
    float4* o = &out[((b * H_OUT + (ih << 1)) * OROW4) + (iw << 5) + cv];

    __stcs(o,                 v);   // (2h,   2w  ) data
    __stcs(o + C4,            z);   // (2h,   2w+1) zero
    __stcs(o + OROW4,         z);   // (2h+1, 2w  ) zero
    __stcs(o + OROW4 + C4,    z);   // (2h+1, 2w+1) zero
}

extern "C" void kernel_launch(void* const* d_in, const int* in_sizes, int n_in,
                              void* d_out, int out_size) {
    const float4* x = (const float4*)d_in[0];
    float4* out = (float4*)d_out;

    dim3 grid(IROW4 / TPB, H_IN, 32);   // (7, 112, 32)
    unpool_kernel<<<grid, TPB>>>(x, out);
}